// round 14
// baseline (speedup 1.0000x reference)
#include <cuda_runtime.h>
#include <cuda_fp16.h>
#include <math.h>
#include <stdint.h>

#define N_NODES   50000
#define N_EDGES   1600000
#define N_FEAT    128
#define EMB       128
#define N_CLASSES 10
#define N_GRAPHS  512
#define ELL_W     128      // max in-degree slot count (true max ~58 for this dist)

// ---------------- device scratch (static, no runtime allocation) ----------------
__device__ int     g_cnt[N_NODES];                  // in-degree (excl. self loop)
__device__ int     g_ell[(size_t)N_NODES * ELL_W];  // ELL adjacency (PRE-SHIFTED src byte offsets: src<<7)
__device__ __half  g_WT[3 * 128 * 128];             // weights fp16, transposed [n][k]
__device__ uint8_t g_bufA8[(size_t)N_NODES * EMB];  // pre-scaled GEMM output (fp8 e4m3)
__device__ __half  g_bufB[(size_t)N_NODES * EMB];   // activation (fp16)
__device__ float   g_pooled[N_GRAPHS * EMB];

// ---------------- fp8 helpers ----------------
__device__ __forceinline__ uint16_t f32x2_to_fp8x2(float lo, float hi) {
    uint16_t r;
    asm("cvt.rn.satfinite.e4m3x2.f32 %0, %2, %1;" : "=h"(r) : "f"(lo), "f"(hi));
    return r;   // lo -> bits[0:8], hi -> bits[8:16]
}

// decode 4 packed e4m3 (u32) -> two f16x2 (as u32 regs)
__device__ __forceinline__ void fp8_dec(uint32_t u, uint32_t& lo, uint32_t& hi) {
    asm("{\n\t"
        ".reg .b16 a, b;\n\t"
        "mov.b32 {a, b}, %2;\n\t"
        "cvt.rn.f16x2.e4m3x2 %0, a;\n\t"
        "cvt.rn.f16x2.e4m3x2 %1, b;\n\t"
        "}"
        : "=r"(lo), "=r"(hi) : "r"(u));
}

__device__ __forceinline__ uint32_t hadd2_bits(uint32_t a, uint32_t b) {
    __half2 r = __hadd2(*(__half2*)&a, *(__half2*)&b);
    return *(uint32_t*)&r;
}

// accumulate one uint2 (8 fp8) into 4 half2 chains
__device__ __forceinline__ void acc_edge2(uint32_t ch[4], uint2 u) {
    uint32_t w[4];
    fp8_dec(u.x, w[0], w[1]);
    fp8_dec(u.y, w[2], w[3]);
#pragma unroll
    for (int k = 0; k < 4; ++k) ch[k] = hadd2_bits(ch[k], w[k]);
}

// ---------------- pre-pass: zero cnt + prep weights ----------------
#define ZERO_BLOCKS  196
#define PREP_BLOCKS  192    // 3*16384 / 256

__global__ void k_pre(const float* __restrict__ W0,
                      const float* __restrict__ W1,
                      const float* __restrict__ W2) {
    const int b = blockIdx.x;
    const int tid = threadIdx.x;
    if (b < ZERO_BLOCKS) {
        int i = b * 256 + tid;
        if (i < N_NODES) g_cnt[i] = 0;
    } else {
        int i = (b - ZERO_BLOCKS) * 256 + tid;   // 0..49151
        int l = i >> 14, r = i & 16383;
        int k = r >> 7, n = r & 127;
        const float* W = (l == 0) ? W0 : (l == 1) ? W1 : W2;
        g_WT[l * 16384 + n * 128 + k] = __float2half(W[k * 128 + n]);
    }
}

// ---------------- adjacency build (single atomic pass, ELL, pre-shifted) -----------
__global__ void k_fill(const int* __restrict__ ei) {
    int i = (blockIdx.x * blockDim.x + threadIdx.x) * 8;
    if (i + 7 < N_EDGES) {
        int4 s0 = *(const int4*)&ei[i];
        int4 s1 = *(const int4*)&ei[i + 4];
        int4 d0 = *(const int4*)&ei[N_EDGES + i];
        int4 d1 = *(const int4*)&ei[N_EDGES + i + 4];
        int p0 = atomicAdd(&g_cnt[d0.x], 1);
        int p1 = atomicAdd(&g_cnt[d0.y], 1);
        int p2 = atomicAdd(&g_cnt[d0.z], 1);
        int p3 = atomicAdd(&g_cnt[d0.w], 1);
        int p4 = atomicAdd(&g_cnt[d1.x], 1);
        int p5 = atomicAdd(&g_cnt[d1.y], 1);
        int p6 = atomicAdd(&g_cnt[d1.z], 1);
        int p7 = atomicAdd(&g_cnt[d1.w], 1);
        if (p0 < ELL_W) g_ell[(size_t)d0.x * ELL_W + p0] = s0.x << 7;
        if (p1 < ELL_W) g_ell[(size_t)d0.y * ELL_W + p1] = s0.y << 7;
        if (p2 < ELL_W) g_ell[(size_t)d0.z * ELL_W + p2] = s0.z << 7;
        if (p3 < ELL_W) g_ell[(size_t)d0.w * ELL_W + p3] = s0.w << 7;
        if (p4 < ELL_W) g_ell[(size_t)d1.x * ELL_W + p4] = s1.x << 7;
        if (p5 < ELL_W) g_ell[(size_t)d1.y * ELL_W + p5] = s1.y << 7;
        if (p6 < ELL_W) g_ell[(size_t)d1.z * ELL_W + p6] = s1.z << 7;
        if (p7 < ELL_W) g_ell[(size_t)d1.w * ELL_W + p7] = s1.w << 7;
    }
}

// ---------------- fp16 tensor-core GEMM, fp8 epilogue ----------------
// g_bufA8[r] = fp8( rsqrt(cnt[r]+1) * (A[r] @ W) ),  A = x fp32 (layer 0) or g_bufB
#define SWT_STRIDE 136
#define N_TILES    ((N_NODES + 127) / 128)   // 391

template <bool EXT_A>
__global__ __launch_bounds__(256, 3) void k_gemm(const float* __restrict__ A_f32,
                                                 int widx) {
    __shared__ __half sWT[128 * SWT_STRIDE];

    const int tid  = threadIdx.x;
    const int warp = tid >> 5;
    const int lane = tid & 31;
    const int grp  = lane >> 2;   // 0..7
    const int q    = lane & 3;    // 0..3

    // stage pre-transposed fp16 W: 2048 uint4 copies (8 per thread)
    {
        const uint4* src = (const uint4*)(g_WT + widx * 16384);
#pragma unroll
        for (int i = 0; i < 8; ++i) {
            int idx = tid + i * 256;
            int n   = idx >> 4;
            int c8  = (idx & 15) * 8;
            *(uint4*)&sWT[n * SWT_STRIDE + c8] = src[idx];
        }
    }

    const int r0 = blockIdx.x * 128 + warp * 16 + grp;   // rows r0, r0+8
    const bool v0 = (r0 < N_NODES);
    const bool v1 = (r0 + 8 < N_NODES);

    float c[16][4];
#pragma unroll
    for (int nt = 0; nt < 16; ++nt)
#pragma unroll
        for (int j = 0; j < 4; ++j) c[nt][j] = 0.f;

    __syncthreads();

#pragma unroll
    for (int chunk = 0; chunk < 2; ++chunk) {
        uint32_t a[4][4];
        if (EXT_A) {
            const float* A0 = A_f32 + (size_t)r0 * EMB;
            const float* A1 = A_f32 + (size_t)(r0 + 8) * EMB;
#pragma unroll
            for (int ks = 0; ks < 4; ++ks) {
                const int ka = chunk * 64 + ks * 16 + 2 * q;
                float2 f0 = v0 ? *(const float2*)&A0[ka]     : make_float2(0.f, 0.f);
                float2 f1 = v1 ? *(const float2*)&A1[ka]     : make_float2(0.f, 0.f);
                float2 f2 = v0 ? *(const float2*)&A0[ka + 8] : make_float2(0.f, 0.f);
                float2 f3 = v1 ? *(const float2*)&A1[ka + 8] : make_float2(0.f, 0.f);
                __half2 h0 = __floats2half2_rn(f0.x, f0.y);
                __half2 h1 = __floats2half2_rn(f1.x, f1.y);
                __half2 h2 = __floats2half2_rn(f2.x, f2.y);
                __half2 h3 = __floats2half2_rn(f3.x, f3.y);
                a[ks][0] = *(uint32_t*)&h0; a[ks][1] = *(uint32_t*)&h1;
                a[ks][2] = *(uint32_t*)&h2; a[ks][3] = *(uint32_t*)&h3;
            }
        } else {
            const __half* A0 = g_bufB + (size_t)r0 * EMB;
            const __half* A1 = g_bufB + (size_t)(r0 + 8) * EMB;
#pragma unroll
            for (int ks = 0; ks < 4; ++ks) {
                const int ka = chunk * 64 + ks * 16 + 2 * q;
                a[ks][0] = v0 ? *(const uint32_t*)&A0[ka]     : 0u;
                a[ks][1] = v1 ? *(const uint32_t*)&A1[ka]     : 0u;
                a[ks][2] = v0 ? *(const uint32_t*)&A0[ka + 8] : 0u;
                a[ks][3] = v1 ? *(const uint32_t*)&A1[ka + 8] : 0u;
            }
        }

#pragma unroll
        for (int ks = 0; ks < 4; ++ks) {
            const int ka = chunk * 64 + ks * 16 + 2 * q;
            const __half* sb = &sWT[grp * SWT_STRIDE + ka];
#pragma unroll
            for (int nt = 0; nt < 16; ++nt) {
                uint32_t b0 = *(const uint32_t*)&sb[nt * 8 * SWT_STRIDE];
                uint32_t b1 = *(const uint32_t*)&sb[nt * 8 * SWT_STRIDE + 8];
                asm volatile(
                    "mma.sync.aligned.m16n8k16.row.col.f32.f16.f16.f32 "
                    "{%0,%1,%2,%3}, {%4,%5,%6,%7}, {%8,%9}, {%0,%1,%2,%3};"
                    : "+f"(c[nt][0]), "+f"(c[nt][1]), "+f"(c[nt][2]), "+f"(c[nt][3])
                    : "r"(a[ks][0]), "r"(a[ks][1]), "r"(a[ks][2]), "r"(a[ks][3]),
                      "r"(b0), "r"(b1));
            }
        }
    }

    // epilogue: scale by rsqrt(deg+1), encode fp8, store u16 (2 cols)
    const float ds0 = v0 ? rsqrtf((float)(g_cnt[r0] + 1))     : 0.f;
    const float ds1 = v1 ? rsqrtf((float)(g_cnt[r0 + 8] + 1)) : 0.f;
    const int ccol = 2 * q;
#pragma unroll
    for (int nt = 0; nt < 16; ++nt) {
        int col = nt * 8 + ccol;
        if (v0) {
            uint16_t p = f32x2_to_fp8x2(ds0 * c[nt][0], ds0 * c[nt][1]);
            *(uint16_t*)&g_bufA8[(size_t)r0 * EMB + col] = p;
        }
        if (v1) {
            uint16_t p = f32x2_to_fp8x2(ds1 * c[nt][2], ds1 * c[nt][3]);
            *(uint16_t*)&g_bufA8[(size_t)(r0 + 8) * EMB + col] = p;
        }
    }
}

// ---------------- aggregation: 4 nodes x 2 feature-halves per warp-pair ------------
// Global warp w: node quad = w>>1, feature half = w&1. Within warp: 8 lanes per
// node (q4 = lane>>3), each lane owns 8 fp8 features (uint2 per edge).
// Doubles warp count vs round 13 (25000 warps) and halves per-warp registers.
template <bool TANH>
__global__ __launch_bounds__(256) void k_agg(const float* __restrict__ bias) {
    const int w = (blockIdx.x * blockDim.x + threadIdx.x) >> 5;
    if (w >= (N_NODES / 4) * 2) return;
    const int lane  = threadIdx.x & 31;
    const int quad  = w >> 1;             // node quad
    const int fhalf = w & 1;              // feature half (0: bytes 0-63, 1: 64-127)
    const int q4 = lane >> 3;             // node within quad
    const int ql = lane & 7;              // lane within node group
    const int d  = quad * 4 + q4;

    const int cnt = g_cnt[d];
    int len = cnt;
    if (len > ELL_W) len = ELL_W;
    const int* __restrict__ cols = g_ell + (size_t)d * ELL_W;        // byte offsets
    const uint8_t* __restrict__ hp = g_bufA8 + fhalf * 64 + ql * 8;  // lane's 8 features

    float acc[8];
#pragma unroll
    for (int k = 0; k < 8; ++k) acc[k] = 0.f;

    int j = 0;
    for (; j + 8 <= len; j += 8) {
        int4 c0 = *(const int4*)&cols[j];
        int4 c1 = *(const int4*)&cols[j + 4];
        uint2 u0 = *(const uint2*)(hp + c0.x);
        uint2 u1 = *(const uint2*)(hp + c0.y);
        uint2 u2 = *(const uint2*)(hp + c0.z);
        uint2 u3 = *(const uint2*)(hp + c0.w);
        uint2 u4 = *(const uint2*)(hp + c1.x);
        uint2 u5 = *(const uint2*)(hp + c1.y);
        uint2 u6 = *(const uint2*)(hp + c1.z);
        uint2 u7 = *(const uint2*)(hp + c1.w);
        uint32_t ch[4];
#pragma unroll
        for (int k = 0; k < 4; ++k) ch[k] = 0u;   // 0x0 == (+0,+0) fp16
        acc_edge2(ch, u0); acc_edge2(ch, u1); acc_edge2(ch, u2); acc_edge2(ch, u3);
        acc_edge2(ch, u4); acc_edge2(ch, u5); acc_edge2(ch, u6); acc_edge2(ch, u7);
#pragma unroll
        for (int k = 0; k < 4; ++k) {
            float2 f = __half22float2(*(__half2*)&ch[k]);
            acc[2 * k]     += f.x;
            acc[2 * k + 1] += f.y;
        }
    }
    if (j < len) {
        // tail: predicated loads (<= 7 edges)
        int4 c0 = *(const int4*)&cols[j];
        int4 c1 = *(const int4*)&cols[j + 4];
        const int cc[8] = {c0.x, c0.y, c0.z, c0.w, c1.x, c1.y, c1.z, c1.w};
        uint32_t ch[4];
#pragma unroll
        for (int k = 0; k < 4; ++k) ch[k] = 0u;
#pragma unroll
        for (int e = 0; e < 8; ++e) {
            uint2 u = make_uint2(0u, 0u);
            if (j + e < len) u = *(const uint2*)(hp + cc[e]);
            acc_edge2(ch, u);
        }
#pragma unroll
        for (int k = 0; k < 4; ++k) {
            float2 f = __half22float2(*(__half2*)&ch[k]);
            acc[2 * k]     += f.x;
            acc[2 * k + 1] += f.y;
        }
    }

    // self loop h'[d]
    {
        uint2 u = *(const uint2*)(hp + (d << 7));
        uint32_t w0, w1, w2, w3;
        fp8_dec(u.x, w0, w1);
        fp8_dec(u.y, w2, w3);
        float2 f0 = __half22float2(*(__half2*)&w0);
        float2 f1 = __half22float2(*(__half2*)&w1);
        float2 f2 = __half22float2(*(__half2*)&w2);
        float2 f3 = __half22float2(*(__half2*)&w3);
        acc[0] += f0.x; acc[1] += f0.y;
        acc[2] += f1.x; acc[3] += f1.y;
        acc[4] += f2.x; acc[5] += f2.y;
        acc[6] += f3.x; acc[7] += f3.y;
    }

    const float dd = rsqrtf((float)(cnt + 1));
    const float* bp = bias + fhalf * 64 + ql * 8;
    float r[8];
#pragma unroll
    for (int k = 0; k < 8; ++k) r[k] = dd * acc[k] + bp[k];
    if (TANH) {
#pragma unroll
        for (int k = 0; k < 8; ++k) r[k] = tanhf(r[k]);
    }
    __half2 h0 = __floats2half2_rn(r[0], r[1]);
    __half2 h1 = __floats2half2_rn(r[2], r[3]);
    __half2 h2 = __floats2half2_rn(r[4], r[5]);
    __half2 h3 = __floats2half2_rn(r[6], r[7]);
    uint4 o;
    o.x = *(uint32_t*)&h0; o.y = *(uint32_t*)&h1;
    o.z = *(uint32_t*)&h2; o.w = *(uint32_t*)&h3;
    *(uint4*)(g_bufB + (size_t)d * EMB + fhalf * 64 + ql * 8) = o;
}

// ---------------- global mean pool (batch sorted, int32 graph ids) ----------------
__device__ __forceinline__ int lower_bound_i(const int* a, int n, int v) {
    int lo = 0, hi = n;
    while (lo < hi) {
        int mid = (lo + hi) >> 1;
        if (a[mid] < v) lo = mid + 1; else hi = mid;
    }
    return lo;
}

__global__ void k_pool(const int* __restrict__ batch) {
    const int g = blockIdx.x;      // 512 blocks
    const int t = threadIdx.x;     // 128 threads
    __shared__ int s_beg, s_end;
    if (t == 0) s_beg = lower_bound_i(batch, N_NODES, g);
    if (t == 1) s_end = lower_bound_i(batch, N_NODES, g + 1);
    __syncthreads();
    const int beg = s_beg, end = s_end;
    float sum = 0.f;
    for (int n = beg; n < end; ++n) sum += __half2float(g_bufB[(size_t)n * EMB + t]);
    int cnt = end - beg; if (cnt < 1) cnt = 1;
    g_pooled[g * EMB + t] = sum / (float)cnt;
}

// ---------------- logits + log_softmax (warp per graph) ----------------
__global__ void k_logits(const float* __restrict__ Wout, const float* __restrict__ bout,
                         float* __restrict__ out) {
    const int warp = (blockIdx.x * blockDim.x + threadIdx.x) >> 5;
    const int lane = threadIdx.x & 31;
    if (warp >= N_GRAPHS) return;

    float4 p = *(const float4*)&g_pooled[warp * EMB + lane * 4];
    const int k0 = lane * 4;

    float logit[N_CLASSES];
#pragma unroll
    for (int c = 0; c < N_CLASSES; ++c) {
        float s = p.x * Wout[(k0 + 0) * N_CLASSES + c]
                + p.y * Wout[(k0 + 1) * N_CLASSES + c]
                + p.z * Wout[(k0 + 2) * N_CLASSES + c]
                + p.w * Wout[(k0 + 3) * N_CLASSES + c];
#pragma unroll
        for (int o = 16; o > 0; o >>= 1) s += __shfl_xor_sync(0xffffffffu, s, o);
        logit[c] = s + bout[c];
    }
    float m = logit[0];
#pragma unroll
    for (int c = 1; c < N_CLASSES; ++c) m = fmaxf(m, logit[c]);
    float se = 0.f;
#pragma unroll
    for (int c = 0; c < N_CLASSES; ++c) se += expf(logit[c] - m);
    float lse = m + logf(se);
    if (lane < N_CLASSES) out[warp * N_CLASSES + lane] = logit[lane] - lse;
}

// ---------------- launch ----------------
extern "C" void kernel_launch(void* const* d_in, const int* in_sizes, int n_in,
                              void* d_out, int out_size) {
    const float* x     = (const float*)d_in[0];
    const int*   ei    = (const int*)d_in[1];    // int32 (JAX x64 disabled)
    const int*   batch = (const int*)d_in[2];
    const float* W0 = (const float*)d_in[3];
    const float* b0 = (const float*)d_in[4];
    const float* W1 = (const float*)d_in[5];
    const float* b1 = (const float*)d_in[6];
    const float* W2 = (const float*)d_in[7];
    const float* b2 = (const float*)d_in[8];
    const float* Wout = (const float*)d_in[9];
    const float* bout = (const float*)d_in[10];
    float* out = (float*)d_out;

    // pre-pass (zero cnt + weight prep) + adjacency build
    k_pre<<<ZERO_BLOCKS + PREP_BLOCKS, 256>>>(W0, W1, W2);
    k_fill<<<(N_EDGES / 8 + 255) / 256, 256>>>(ei);

    // 4 nodes x 2 feature-halves per warp-pair -> 25000 warps -> 3125 blocks
    const int agg_blocks = ((N_NODES / 4) * 2 * 32 + 255) / 256;

    // layer 0
    k_gemm<true><<<N_TILES, 256>>>(x, 0);
    k_agg<true><<<agg_blocks, 256>>>(b0);
    // layer 1
    k_gemm<false><<<N_TILES, 256>>>(nullptr, 1);
    k_agg<true><<<agg_blocks, 256>>>(b1);
    // layer 2 (no tanh)
    k_gemm<false><<<N_TILES, 256>>>(nullptr, 2);
    k_agg<false><<<agg_blocks, 256>>>(b2);

    // pool + classifier
    k_pool<<<N_GRAPHS, EMB>>>(batch);
    k_logits<<<(N_GRAPHS * 32 + 127) / 128, 128>>>(Wout, bout, out);
}

// round 16
// speedup vs baseline: 1.1135x; 1.1135x over previous
#include <cuda_runtime.h>
#include <cuda_fp16.h>
#include <math.h>
#include <stdint.h>

#define N_NODES   50000
#define N_EDGES   1600000
#define N_FEAT    128
#define EMB       128
#define N_CLASSES 10
#define N_GRAPHS  512
#define ELL_W     128      // max in-degree slot count (true max ~58 for this dist)

// ---------------- device scratch (static, no runtime allocation) ----------------
__device__ int     g_cnt[N_NODES];                  // in-degree (excl. self loop)
__device__ int     g_ell[(size_t)N_NODES * ELL_W];  // ELL adjacency (PRE-SHIFTED src byte offsets: src<<7)
__device__ __half  g_WT[3 * 128 * 128];             // weights fp16, transposed [n][k]
__device__ uint8_t g_bufA8[(size_t)N_NODES * EMB];  // pre-scaled GEMM output (fp8 e4m3)
__device__ __half  g_bufB[(size_t)N_NODES * EMB];   // activation (fp16)

// ---------------- fp8 helpers ----------------
__device__ __forceinline__ uint16_t f32x2_to_fp8x2(float lo, float hi) {
    uint16_t r;
    asm("cvt.rn.satfinite.e4m3x2.f32 %0, %2, %1;" : "=h"(r) : "f"(lo), "f"(hi));
    return r;   // lo -> bits[0:8], hi -> bits[8:16]
}

// decode 4 packed e4m3 (u32) -> two f16x2 (as u32 regs)
__device__ __forceinline__ void fp8_dec(uint32_t u, uint32_t& lo, uint32_t& hi) {
    asm("{\n\t"
        ".reg .b16 a, b;\n\t"
        "mov.b32 {a, b}, %2;\n\t"
        "cvt.rn.f16x2.e4m3x2 %0, a;\n\t"
        "cvt.rn.f16x2.e4m3x2 %1, b;\n\t"
        "}"
        : "=r"(lo), "=r"(hi) : "r"(u));
}

__device__ __forceinline__ uint32_t hadd2_bits(uint32_t a, uint32_t b) {
    __half2 r = __hadd2(*(__half2*)&a, *(__half2*)&b);
    return *(uint32_t*)&r;
}

// accumulate one uint4 (16 fp8) into 8 half2 chains
__device__ __forceinline__ void acc_edge(uint32_t ch[8], uint4 u) {
    uint32_t w[8];
    fp8_dec(u.x, w[0], w[1]);
    fp8_dec(u.y, w[2], w[3]);
    fp8_dec(u.z, w[4], w[5]);
    fp8_dec(u.w, w[6], w[7]);
#pragma unroll
    for (int k = 0; k < 8; ++k) ch[k] = hadd2_bits(ch[k], w[k]);
}

// ---------------- pre-pass: zero cnt + prep weights ----------------
#define ZERO_BLOCKS  196
#define PREP_BLOCKS  192    // 3*16384 / 256

__global__ void k_pre(const float* __restrict__ W0,
                      const float* __restrict__ W1,
                      const float* __restrict__ W2) {
    const int b = blockIdx.x;
    const int tid = threadIdx.x;
    if (b < ZERO_BLOCKS) {
        int i = b * 256 + tid;
        if (i < N_NODES) g_cnt[i] = 0;
    } else {
        int i = (b - ZERO_BLOCKS) * 256 + tid;   // 0..49151
        int l = i >> 14, r = i & 16383;
        int k = r >> 7, n = r & 127;
        const float* W = (l == 0) ? W0 : (l == 1) ? W1 : W2;
        g_WT[l * 16384 + n * 128 + k] = __float2half(W[k * 128 + n]);
    }
}

// ---------------- adjacency build (single atomic pass, ELL, pre-shifted) -----------
__global__ void k_fill(const int* __restrict__ ei) {
    int i = (blockIdx.x * blockDim.x + threadIdx.x) * 8;
    if (i + 7 < N_EDGES) {
        int4 s0 = *(const int4*)&ei[i];
        int4 s1 = *(const int4*)&ei[i + 4];
        int4 d0 = *(const int4*)&ei[N_EDGES + i];
        int4 d1 = *(const int4*)&ei[N_EDGES + i + 4];
        int p0 = atomicAdd(&g_cnt[d0.x], 1);
        int p1 = atomicAdd(&g_cnt[d0.y], 1);
        int p2 = atomicAdd(&g_cnt[d0.z], 1);
        int p3 = atomicAdd(&g_cnt[d0.w], 1);
        int p4 = atomicAdd(&g_cnt[d1.x], 1);
        int p5 = atomicAdd(&g_cnt[d1.y], 1);
        int p6 = atomicAdd(&g_cnt[d1.z], 1);
        int p7 = atomicAdd(&g_cnt[d1.w], 1);
        if (p0 < ELL_W) g_ell[(size_t)d0.x * ELL_W + p0] = s0.x << 7;
        if (p1 < ELL_W) g_ell[(size_t)d0.y * ELL_W + p1] = s0.y << 7;
        if (p2 < ELL_W) g_ell[(size_t)d0.z * ELL_W + p2] = s0.z << 7;
        if (p3 < ELL_W) g_ell[(size_t)d0.w * ELL_W + p3] = s0.w << 7;
        if (p4 < ELL_W) g_ell[(size_t)d1.x * ELL_W + p4] = s1.x << 7;
        if (p5 < ELL_W) g_ell[(size_t)d1.y * ELL_W + p5] = s1.y << 7;
        if (p6 < ELL_W) g_ell[(size_t)d1.z * ELL_W + p6] = s1.z << 7;
        if (p7 < ELL_W) g_ell[(size_t)d1.w * ELL_W + p7] = s1.w << 7;
    }
}

// ---------------- fp16 tensor-core GEMM, fp8 epilogue ----------------
// g_bufA8[r] = fp8( rsqrt(cnt[r]+1) * (A[r] @ W) ),  A = x fp32 (layer 0) or g_bufB
#define SWT_STRIDE 136
#define N_TILES    ((N_NODES + 127) / 128)   // 391

template <bool EXT_A>
__global__ __launch_bounds__(256, 3) void k_gemm(const float* __restrict__ A_f32,
                                                 int widx) {
    __shared__ __half sWT[128 * SWT_STRIDE];

    const int tid  = threadIdx.x;
    const int warp = tid >> 5;
    const int lane = tid & 31;
    const int grp  = lane >> 2;   // 0..7
    const int q    = lane & 3;    // 0..3

    // stage pre-transposed fp16 W: 2048 uint4 copies (8 per thread)
    {
        const uint4* src = (const uint4*)(g_WT + widx * 16384);
#pragma unroll
        for (int i = 0; i < 8; ++i) {
            int idx = tid + i * 256;
            int n   = idx >> 4;
            int c8  = (idx & 15) * 8;
            *(uint4*)&sWT[n * SWT_STRIDE + c8] = src[idx];
        }
    }

    const int r0 = blockIdx.x * 128 + warp * 16 + grp;   // rows r0, r0+8
    const bool v0 = (r0 < N_NODES);
    const bool v1 = (r0 + 8 < N_NODES);

    float c[16][4];
#pragma unroll
    for (int nt = 0; nt < 16; ++nt)
#pragma unroll
        for (int j = 0; j < 4; ++j) c[nt][j] = 0.f;

    __syncthreads();

#pragma unroll
    for (int chunk = 0; chunk < 2; ++chunk) {
        uint32_t a[4][4];
        if (EXT_A) {
            const float* A0 = A_f32 + (size_t)r0 * EMB;
            const float* A1 = A_f32 + (size_t)(r0 + 8) * EMB;
#pragma unroll
            for (int ks = 0; ks < 4; ++ks) {
                const int ka = chunk * 64 + ks * 16 + 2 * q;
                float2 f0 = v0 ? *(const float2*)&A0[ka]     : make_float2(0.f, 0.f);
                float2 f1 = v1 ? *(const float2*)&A1[ka]     : make_float2(0.f, 0.f);
                float2 f2 = v0 ? *(const float2*)&A0[ka + 8] : make_float2(0.f, 0.f);
                float2 f3 = v1 ? *(const float2*)&A1[ka + 8] : make_float2(0.f, 0.f);
                __half2 h0 = __floats2half2_rn(f0.x, f0.y);
                __half2 h1 = __floats2half2_rn(f1.x, f1.y);
                __half2 h2 = __floats2half2_rn(f2.x, f2.y);
                __half2 h3 = __floats2half2_rn(f3.x, f3.y);
                a[ks][0] = *(uint32_t*)&h0; a[ks][1] = *(uint32_t*)&h1;
                a[ks][2] = *(uint32_t*)&h2; a[ks][3] = *(uint32_t*)&h3;
            }
        } else {
            const __half* A0 = g_bufB + (size_t)r0 * EMB;
            const __half* A1 = g_bufB + (size_t)(r0 + 8) * EMB;
#pragma unroll
            for (int ks = 0; ks < 4; ++ks) {
                const int ka = chunk * 64 + ks * 16 + 2 * q;
                a[ks][0] = v0 ? *(const uint32_t*)&A0[ka]     : 0u;
                a[ks][1] = v1 ? *(const uint32_t*)&A1[ka]     : 0u;
                a[ks][2] = v0 ? *(const uint32_t*)&A0[ka + 8] : 0u;
                a[ks][3] = v1 ? *(const uint32_t*)&A1[ka + 8] : 0u;
            }
        }

#pragma unroll
        for (int ks = 0; ks < 4; ++ks) {
            const int ka = chunk * 64 + ks * 16 + 2 * q;
            const __half* sb = &sWT[grp * SWT_STRIDE + ka];
#pragma unroll
            for (int nt = 0; nt < 16; ++nt) {
                uint32_t b0 = *(const uint32_t*)&sb[nt * 8 * SWT_STRIDE];
                uint32_t b1 = *(const uint32_t*)&sb[nt * 8 * SWT_STRIDE + 8];
                asm volatile(
                    "mma.sync.aligned.m16n8k16.row.col.f32.f16.f16.f32 "
                    "{%0,%1,%2,%3}, {%4,%5,%6,%7}, {%8,%9}, {%0,%1,%2,%3};"
                    : "+f"(c[nt][0]), "+f"(c[nt][1]), "+f"(c[nt][2]), "+f"(c[nt][3])
                    : "r"(a[ks][0]), "r"(a[ks][1]), "r"(a[ks][2]), "r"(a[ks][3]),
                      "r"(b0), "r"(b1));
            }
        }
    }

    // epilogue: scale by rsqrt(deg+1), encode fp8, store u16 (2 cols)
    const float ds0 = v0 ? rsqrtf((float)(g_cnt[r0] + 1))     : 0.f;
    const float ds1 = v1 ? rsqrtf((float)(g_cnt[r0 + 8] + 1)) : 0.f;
    const int ccol = 2 * q;
#pragma unroll
    for (int nt = 0; nt < 16; ++nt) {
        int col = nt * 8 + ccol;
        if (v0) {
            uint16_t p = f32x2_to_fp8x2(ds0 * c[nt][0], ds0 * c[nt][1]);
            *(uint16_t*)&g_bufA8[(size_t)r0 * EMB + col] = p;
        }
        if (v1) {
            uint16_t p = f32x2_to_fp8x2(ds1 * c[nt][2], ds1 * c[nt][3]);
            *(uint16_t*)&g_bufA8[(size_t)(r0 + 8) * EMB + col] = p;
        }
    }
}

// ---------------- aggregation: FOUR nodes per warp (8 lanes each), fp8 gather ------
// R13 structure; __launch_bounds__(256,5) caps regs at 48 -> 5 CTAs/SM (40 warps).
template <bool TANH>
__global__ __launch_bounds__(256, 5) void k_agg(const float* __restrict__ bias) {
    const int warp = (blockIdx.x * blockDim.x + threadIdx.x) >> 5;
    if (warp * 4 >= N_NODES) return;      // N_NODES % 4 == 0 -> whole warp valid/invalid
    const int lane = threadIdx.x & 31;
    const int q4 = lane >> 3;             // node within warp
    const int ql = lane & 7;              // lane within node group
    const int d  = warp * 4 + q4;

    const int cnt = g_cnt[d];
    int len = cnt;
    if (len > ELL_W) len = ELL_W;
    const int* __restrict__ cols = g_ell + (size_t)d * ELL_W;   // byte offsets
    const uint8_t* __restrict__ hp = g_bufA8 + ql * 16;         // lane's 16 features

    float acc[16];
#pragma unroll
    for (int k = 0; k < 16; ++k) acc[k] = 0.f;

    int j = 0;
    for (; j + 8 <= len; j += 8) {
        int4 c0 = *(const int4*)&cols[j];
        int4 c1 = *(const int4*)&cols[j + 4];
        uint4 u0 = *(const uint4*)(hp + c0.x);
        uint4 u1 = *(const uint4*)(hp + c0.y);
        uint4 u2 = *(const uint4*)(hp + c0.z);
        uint4 u3 = *(const uint4*)(hp + c0.w);
        uint4 u4 = *(const uint4*)(hp + c1.x);
        uint4 u5 = *(const uint4*)(hp + c1.y);
        uint4 u6 = *(const uint4*)(hp + c1.z);
        uint4 u7 = *(const uint4*)(hp + c1.w);
        uint32_t ch[8];
#pragma unroll
        for (int k = 0; k < 8; ++k) ch[k] = 0u;   // 0x0 == (+0,+0) fp16
        acc_edge(ch, u0); acc_edge(ch, u1); acc_edge(ch, u2); acc_edge(ch, u3);
        acc_edge(ch, u4); acc_edge(ch, u5); acc_edge(ch, u6); acc_edge(ch, u7);
#pragma unroll
        for (int k = 0; k < 8; ++k) {
            float2 f = __half22float2(*(__half2*)&ch[k]);
            acc[2 * k]     += f.x;
            acc[2 * k + 1] += f.y;
        }
    }
    if (j < len) {
        // tail: predicated loads (<= 7 edges)
        int4 c0 = *(const int4*)&cols[j];
        int4 c1 = *(const int4*)&cols[j + 4];
        const int cc[8] = {c0.x, c0.y, c0.z, c0.w, c1.x, c1.y, c1.z, c1.w};
        uint32_t ch[8];
#pragma unroll
        for (int k = 0; k < 8; ++k) ch[k] = 0u;
#pragma unroll
        for (int e = 0; e < 8; ++e) {
            uint4 u = make_uint4(0u, 0u, 0u, 0u);
            if (j + e < len) u = *(const uint4*)(hp + cc[e]);
            acc_edge(ch, u);
        }
#pragma unroll
        for (int k = 0; k < 8; ++k) {
            float2 f = __half22float2(*(__half2*)&ch[k]);
            acc[2 * k]     += f.x;
            acc[2 * k + 1] += f.y;
        }
    }

    // self loop h'[d]
    {
        uint4 u = *(const uint4*)(hp + (d << 7));
        uint32_t w[8];
        fp8_dec(u.x, w[0], w[1]);
        fp8_dec(u.y, w[2], w[3]);
        fp8_dec(u.z, w[4], w[5]);
        fp8_dec(u.w, w[6], w[7]);
#pragma unroll
        for (int k = 0; k < 8; ++k) {
            float2 f = __half22float2(*(__half2*)&w[k]);
            acc[2 * k]     += f.x;
            acc[2 * k + 1] += f.y;
        }
    }

    const float dd = rsqrtf((float)(cnt + 1));
    const float* bp = bias + ql * 16;
    float r[16];
#pragma unroll
    for (int k = 0; k < 16; ++k) r[k] = dd * acc[k] + bp[k];
    if (TANH) {
#pragma unroll
        for (int k = 0; k < 16; ++k) r[k] = tanhf(r[k]);
    }
    uint4 o0, o1;
    {
        __half2 h0 = __floats2half2_rn(r[0], r[1]);
        __half2 h1 = __floats2half2_rn(r[2], r[3]);
        __half2 h2 = __floats2half2_rn(r[4], r[5]);
        __half2 h3 = __floats2half2_rn(r[6], r[7]);
        o0.x = *(uint32_t*)&h0; o0.y = *(uint32_t*)&h1;
        o0.z = *(uint32_t*)&h2; o0.w = *(uint32_t*)&h3;
        __half2 h4 = __floats2half2_rn(r[8], r[9]);
        __half2 h5 = __floats2half2_rn(r[10], r[11]);
        __half2 h6 = __floats2half2_rn(r[12], r[13]);
        __half2 h7 = __floats2half2_rn(r[14], r[15]);
        o1.x = *(uint32_t*)&h4; o1.y = *(uint32_t*)&h5;
        o1.z = *(uint32_t*)&h6; o1.w = *(uint32_t*)&h7;
    }
    __half* outp = g_bufB + (size_t)d * EMB + ql * 16;
    *(uint4*)outp = o0;
    *(uint4*)(outp + 8) = o1;
}

// ---------------- fused pool + logits (block per graph) ----------------
__device__ __forceinline__ int lower_bound_i(const int* a, int n, int v) {
    int lo = 0, hi = n;
    while (lo < hi) {
        int mid = (lo + hi) >> 1;
        if (a[mid] < v) lo = mid + 1; else hi = mid;
    }
    return lo;
}

__global__ void k_pool_logits(const int* __restrict__ batch,
                              const float* __restrict__ Wout,
                              const float* __restrict__ bout,
                              float* __restrict__ out) {
    const int g = blockIdx.x;      // 512 blocks
    const int t = threadIdx.x;     // 128 threads
    __shared__ __align__(16) float s_pool[EMB];   // 16B-aligned for float4 reads
    __shared__ int s_beg, s_end;
    if (t == 0) s_beg = lower_bound_i(batch, N_NODES, g);
    if (t == 1) s_end = lower_bound_i(batch, N_NODES, g + 1);
    __syncthreads();
    const int beg = s_beg, end = s_end;
    float sum = 0.f;
    for (int n = beg; n < end; ++n) sum += __half2float(g_bufB[(size_t)n * EMB + t]);
    int cnt = end - beg; if (cnt < 1) cnt = 1;
    s_pool[t] = sum / (float)cnt;
    __syncthreads();

    if (t < 32) {
        const int lane = t;
        float4 p = *(const float4*)&s_pool[lane * 4];
        const int k0 = lane * 4;

        float logit[N_CLASSES];
#pragma unroll
        for (int c = 0; c < N_CLASSES; ++c) {
            float s = p.x * Wout[(k0 + 0) * N_CLASSES + c]
                    + p.y * Wout[(k0 + 1) * N_CLASSES + c]
                    + p.z * Wout[(k0 + 2) * N_CLASSES + c]
                    + p.w * Wout[(k0 + 3) * N_CLASSES + c];
#pragma unroll
            for (int o = 16; o > 0; o >>= 1) s += __shfl_xor_sync(0xffffffffu, s, o);
            logit[c] = s + bout[c];
        }
        float m = logit[0];
#pragma unroll
        for (int c = 1; c < N_CLASSES; ++c) m = fmaxf(m, logit[c]);
        float se = 0.f;
#pragma unroll
        for (int c = 0; c < N_CLASSES; ++c) se += expf(logit[c] - m);
        float lse = m + logf(se);
        if (lane < N_CLASSES) out[g * N_CLASSES + lane] = logit[lane] - lse;
    }
}

// ---------------- launch ----------------
extern "C" void kernel_launch(void* const* d_in, const int* in_sizes, int n_in,
                              void* d_out, int out_size) {
    const float* x     = (const float*)d_in[0];
    const int*   ei    = (const int*)d_in[1];    // int32 (JAX x64 disabled)
    const int*   batch = (const int*)d_in[2];
    const float* W0 = (const float*)d_in[3];
    const float* b0 = (const float*)d_in[4];
    const float* W1 = (const float*)d_in[5];
    const float* b1 = (const float*)d_in[6];
    const float* W2 = (const float*)d_in[7];
    const float* b2 = (const float*)d_in[8];
    const float* Wout = (const float*)d_in[9];
    const float* bout = (const float*)d_in[10];
    float* out = (float*)d_out;

    // pre-pass (zero cnt + weight prep) + adjacency build
    k_pre<<<ZERO_BLOCKS + PREP_BLOCKS, 256>>>(W0, W1, W2);
    k_fill<<<(N_EDGES / 8 + 255) / 256, 256>>>(ei);

    // four nodes per warp -> 12500 warps -> 1563 blocks of 256
    const int agg_blocks = ((N_NODES + 3) / 4 * 32 + 255) / 256;

    // layer 0
    k_gemm<true><<<N_TILES, 256>>>(x, 0);
    k_agg<true><<<agg_blocks, 256>>>(b0);
    // layer 1
    k_gemm<false><<<N_TILES, 256>>>(nullptr, 1);
    k_agg<true><<<agg_blocks, 256>>>(b1);
    // layer 2 (no tanh)
    k_gemm<false><<<N_TILES, 256>>>(nullptr, 2);
    k_agg<false><<<agg_blocks, 256>>>(b2);

    // fused pool + classifier
    k_pool_logits<<<N_GRAPHS, EMB>>>(batch, Wout, bout, out);
}